// round 9
// baseline (speedup 1.0000x reference)
#include <cuda_runtime.h>
#include <cuda_bf16.h>
#include <cstdint>

// Problem constants
#define T_STEPS 500
#define B_SZ    128
#define K_SZ    256
#define F_SZ    512
#define C_SZ    10
#define MROWS   (T_STEPS * B_SZ)   // 64000
#define NEURONS (B_SZ * F_SZ)      // 65536

// Time split for GEMM/scan overlap
#define T_SPLIT 380                 // divisible by 20; GEMM_A covers mtiles [0,380)

// GEMM tiling: CTA 128x128, 8 warps of 64x32, KC=64.
#define TM 128
#define TN 128
#define KC 64
#define NCHUNK (K_SZ / KC)   // 4
#define GT 256

// Padded smem rows: 64 bf16 (128B) + 16B pad = 144 B
#define PITCHB     144
#define TILEBYTES  (128 * PITCHB)      // 18432
#define A_HI 0
#define A_LO TILEBYTES
#define B_HI (2 * TILEBYTES)
#define B_LO (3 * TILEBYTES)
#define STAGEBYTES (4 * TILEBYTES)     // 73728
#define SMEM_TOTAL (2 * STAGEBYTES)    // 147456

// Scratch
__device__ float g_proj[MROWS * F_SZ];            // 131 MB
__device__ float g_counts[NEURONS];
__device__ float g_u[NEURONS];
__device__ float g_tr[NEURONS];
__device__ __nv_bfloat16 g_whi[F_SZ * K_SZ];
__device__ __nv_bfloat16 g_wlo[F_SZ * K_SZ];

// ---------------- helpers ----------------
__device__ __forceinline__ uint32_t smem_u32(const void* p) {
    uint32_t a;
    asm("{ .reg .u64 t; cvta.to.shared.u64 t, %1; cvt.u32.u64 %0, t; }" : "=r"(a) : "l"(p));
    return a;
}
__device__ __forceinline__ void cp_async16(uint32_t dst, const void* src) {
    asm volatile("cp.async.cg.shared.global [%0], [%1], 16;" :: "r"(dst), "l"(src) : "memory");
}
#define CP_COMMIT() asm volatile("cp.async.commit_group;" ::: "memory")

__device__ __forceinline__ void ldmx4(uint32_t* r, uint32_t addr) {
    asm volatile("ldmatrix.sync.aligned.m8n8.x4.shared.b16 {%0,%1,%2,%3}, [%4];"
                 : "=r"(r[0]), "=r"(r[1]), "=r"(r[2]), "=r"(r[3]) : "r"(addr));
}
__device__ __forceinline__ void mma_bf16(float* c, const uint32_t* a, const uint32_t* b) {
    asm volatile(
        "mma.sync.aligned.m16n8k16.row.col.f32.bf16.bf16.f32 "
        "{%0,%1,%2,%3}, {%4,%5,%6,%7}, {%8,%9}, {%0,%1,%2,%3};"
        : "+f"(c[0]), "+f"(c[1]), "+f"(c[2]), "+f"(c[3])
        : "r"(a[0]), "r"(a[1]), "r"(a[2]), "r"(a[3]), "r"(b[0]), "r"(b[1]));
}
__device__ __forceinline__ void split2(float a, float b, uint32_t& hi, uint32_t& lo) {
    __nv_bfloat16 h0 = __float2bfloat16(a), h1 = __float2bfloat16(b);
    __nv_bfloat16 l0 = __float2bfloat16(a - __bfloat162float(h0));
    __nv_bfloat16 l1 = __float2bfloat16(b - __bfloat162float(h1));
    hi = (uint32_t)*(uint16_t*)&h0 | ((uint32_t)*(uint16_t*)&h1 << 16);
    lo = (uint32_t)*(uint16_t*)&l0 | ((uint32_t)*(uint16_t*)&l1 << 16);
}

// ---------------- Pass 0: W fp32 -> bf16 hi/lo (tiny) ----------------
__global__ void convert_w_kernel(const float4* __restrict__ wsrc,
                                 uint2* __restrict__ whi, uint2* __restrict__ wlo, int n4)
{
    int i = blockIdx.x * blockDim.x + threadIdx.x;
    if (i >= n4) return;
    float4 v = wsrc[i];
    uint2 ph, pl;
    split2(v.x, v.y, ph.x, pl.x);
    split2(v.z, v.w, ph.y, pl.y);
    whi[i] = ph;
    wlo[i] = pl;
}

// ---------------- Pass 1: GEMM proj = x @ W^T (A split in-kernel) ----------------
__global__ __launch_bounds__(GT, 1)
void snn_gemm_kernel(const float* __restrict__ x, int mbase)
{
    extern __shared__ char smem[];
    const uint32_t sb = smem_u32(smem);
    const int tid  = threadIdx.x;
    const int lane = tid & 31;
    const int wid  = tid >> 5;
    const int wm   = wid >> 2;
    const int wn   = wid & 3;
    const int mtile = blockIdx.x + mbase;
    const int ntile = blockIdx.y;

    const uint32_t laneoff = (uint32_t)((lane & 15) * PITCHB + (lane >> 4) * 16);

    float acc[4][4][4];
    #pragma unroll
    for (int mi = 0; mi < 4; ++mi)
        #pragma unroll
        for (int ni = 0; ni < 4; ++ni)
            #pragma unroll
            for (int q = 0; q < 4; ++q) acc[mi][ni][q] = 0.f;

    const int br = tid >> 3;
    const int bu = tid & 7;
    auto stageB = [&](int s, int c) {
        #pragma unroll
        for (int pass = 0; pass < 4; ++pass) {
            const int row = pass * 32 + br;
            const uint32_t d = sb + s * STAGEBYTES + row * PITCHB + bu * 16;
            const size_t o = (size_t)(ntile * TN + row) * K_SZ + c * KC + bu * 8;
            cp_async16(d + B_HI, g_whi + o);
            cp_async16(d + B_LO, g_wlo + o);
        }
    };
    auto ldgA = [&](int c, float4* r) {
        #pragma unroll
        for (int i = 0; i < 8; ++i) {
            int v = tid + 256 * i;
            int row = v >> 4, seg = v & 15;
            r[i] = *reinterpret_cast<const float4*>(
                x + (size_t)(mtile * TM + row) * K_SZ + c * KC + seg * 4);
        }
    };
    auto stsA = [&](int s, const float4* r) {
        #pragma unroll
        for (int i = 0; i < 8; ++i) {
            int v = tid + 256 * i;
            int row = v >> 4, seg = v & 15;
            uint2 ph, pl;
            split2(r[i].x, r[i].y, ph.x, pl.x);
            split2(r[i].z, r[i].w, ph.y, pl.y);
            char* d = smem + s * STAGEBYTES + row * PITCHB + seg * 8;
            *reinterpret_cast<uint2*>(d + A_HI) = ph;
            *reinterpret_cast<uint2*>(d + A_LO) = pl;
        }
    };

    float4 ra[8];
    ldgA(0, ra);
    stageB(0, 0);
    CP_COMMIT();
    stsA(0, ra);

    for (int c = 0; c < NCHUNK; ++c) {
        const int s = c & 1;
        float4 rn[8];
        if (c + 1 < NCHUNK) {
            ldgA(c + 1, rn);
            stageB(s ^ 1, c + 1);
            CP_COMMIT();
            asm volatile("cp.async.wait_group 1;" ::: "memory");
        } else {
            asm volatile("cp.async.wait_group 0;" ::: "memory");
        }
        __syncthreads();

        const uint32_t base = sb + s * STAGEBYTES;
        #pragma unroll
        for (int kk = 0; kk < 4; ++kk) {
            uint32_t ah[4][4], al[4][4];
            #pragma unroll
            for (int mi = 0; mi < 4; ++mi) {
                uint32_t addr = base + (uint32_t)((wm * 64 + mi * 16) * PITCHB + kk * 32) + laneoff;
                ldmx4(ah[mi], addr + A_HI);
                ldmx4(al[mi], addr + A_LO);
            }
            uint32_t bh[4][2], bl[4][2];
            #pragma unroll
            for (int p = 0; p < 2; ++p) {
                uint32_t addr = base + (uint32_t)((wn * 32 + p * 16) * PITCHB + kk * 32) + laneoff;
                uint32_t r[4];
                ldmx4(r, addr + B_HI);
                bh[2*p][0] = r[0]; bh[2*p][1] = r[2];
                bh[2*p+1][0] = r[1]; bh[2*p+1][1] = r[3];
                ldmx4(r, addr + B_LO);
                bl[2*p][0] = r[0]; bl[2*p][1] = r[2];
                bl[2*p+1][0] = r[1]; bl[2*p+1][1] = r[3];
            }
            #pragma unroll
            for (int mi = 0; mi < 4; ++mi)
                #pragma unroll
                for (int ni = 0; ni < 4; ++ni) {
                    mma_bf16(acc[mi][ni], ah[mi], bh[ni]);
                    mma_bf16(acc[mi][ni], ah[mi], bl[ni]);
                    mma_bf16(acc[mi][ni], al[mi], bh[ni]);
                }
        }

        if (c + 1 < NCHUNK)
            stsA(s ^ 1, rn);
        __syncthreads();
    }

    const int g  = lane >> 2;
    const int tg = lane & 3;
    #pragma unroll
    for (int mi = 0; mi < 4; ++mi) {
        const int m0 = mtile * TM + wm * 64 + mi * 16 + g;
        #pragma unroll
        for (int ni = 0; ni < 4; ++ni) {
            const int nc = ntile * TN + wn * 32 + ni * 8 + tg * 2;
            *reinterpret_cast<float2*>(&g_proj[(size_t)m0 * F_SZ + nc]) =
                make_float2(acc[mi][ni][0], acc[mi][ni][1]);
            *reinterpret_cast<float2*>(&g_proj[(size_t)(m0 + 8) * F_SZ + nc]) =
                make_float2(acc[mi][ni][2], acc[mi][ni][3]);
        }
    }
}

// ---------------- Pass 2: LIF scan over [t0, t1) with state carry ----------------
__global__ __launch_bounds__(512, 1)
void snn_scan_part(int t0, int t1, int first, int last)
{
    const int n = blockIdx.x * 512 + threadIdx.x;
    const float* p = g_proj + n;
    float u, tr, cnt;
    if (first) { u = 0.f; tr = 0.f; cnt = 0.f; }
    else       { u = g_u[n]; tr = g_tr[n]; cnt = g_counts[n]; }

    #pragma unroll 1
    for (int t = t0; t < t1; t += 20) {          // ranges are multiples of 20
        float v[20];
        #pragma unroll
        for (int j = 0; j < 20; ++j)
            v[j] = __ldcs(p + (size_t)(t + j) * NEURONS);
        #pragma unroll
        for (int j = 0; j < 20; ++j) {
            tr = 0.95f * tr + v[j];
            u  = 0.90f * u + tr;
            if (u > 1.0f) { cnt += 1.0f; u = 0.0f; }
        }
    }

    if (last) {
        g_counts[n] = cnt;
    } else {
        g_u[n] = u; g_tr[n] = tr; g_counts[n] = cnt;
    }
}

// ---------------- Pass 3: decoder ----------------
__global__ __launch_bounds__(320, 1)
void snn_decode_kernel(const float* __restrict__ dec_w,
                       const float* __restrict__ dec_b,
                       float* __restrict__ out)
{
    const int b = blockIdx.x;
    const int c = threadIdx.x >> 5;
    const int l = threadIdx.x & 31;
    const float* cnt = g_counts + (size_t)b * F_SZ;
    const float* dwr = dec_w + (size_t)c * F_SZ;
    float s = 0.f;
    #pragma unroll
    for (int fi = l; fi < F_SZ; fi += 32)
        s += cnt[fi] * dwr[fi];
    #pragma unroll
    for (int o = 16; o > 0; o >>= 1)
        s += __shfl_down_sync(0xffffffffu, s, o);
    if (l == 0)
        out[b * C_SZ + c] = s + dec_b[c];
}

extern "C" void kernel_launch(void* const* d_in, const int* in_sizes, int n_in,
                              void* d_out, int out_size)
{
    const float* x     = (const float*)d_in[0];
    const float* wts   = (const float*)d_in[1];
    const float* dec_w = (const float*)d_in[2];
    const float* dec_b = (const float*)d_in[3];
    float* out = (float*)d_out;

    static uint2* p_whi = nullptr; static uint2* p_wlo = nullptr;
    static cudaStream_t s2 = nullptr;
    static cudaEvent_t evA = nullptr, evB = nullptr;
    if (!p_whi) {
        // One-time init. First harness call is the (non-captured) correctness
        // run, so object creation happens outside graph capture. No device
        // allocations here.
        cudaGetSymbolAddress((void**)&p_whi, g_whi);
        cudaGetSymbolAddress((void**)&p_wlo, g_wlo);
        cudaFuncSetAttribute(snn_gemm_kernel,
                             cudaFuncAttributeMaxDynamicSharedMemorySize, SMEM_TOTAL);
        cudaStreamCreateWithFlags(&s2, cudaStreamNonBlocking);
        cudaEventCreateWithFlags(&evA, cudaEventDisableTiming);
        cudaEventCreateWithFlags(&evB, cudaEventDisableTiming);
    }

    const int nw4 = F_SZ * K_SZ / 4;    // 32768
    convert_w_kernel<<<(nw4 + 255) / 256, 256>>>((const float4*)wts, p_whi, p_wlo, nw4);

    // GEMM part A: mtiles [0, T_SPLIT)
    dim3 gridA(T_SPLIT, F_SZ / TN);
    snn_gemm_kernel<<<gridA, GT, SMEM_TOTAL>>>(x, 0);
    cudaEventRecord(evA, 0);

    // GEMM part B on the main stream, scan part A concurrently on s2.
    dim3 gridB(T_STEPS - T_SPLIT, F_SZ / TN);
    snn_gemm_kernel<<<gridB, GT, SMEM_TOTAL>>>(x, T_SPLIT);

    cudaStreamWaitEvent(s2, evA, 0);
    snn_scan_part<<<NEURONS / 512, 512, 0, s2>>>(0, T_SPLIT, 1, 0);
    cudaEventRecord(evB, s2);

    // Join: scan part B needs GEMM_B (stream order) and scan_A (event).
    cudaStreamWaitEvent(0, evB, 0);
    snn_scan_part<<<NEURONS / 512, 512>>>(T_SPLIT, T_STEPS, 0, 1);
    snn_decode_kernel<<<B_SZ, 320>>>(dec_w, dec_b, out);
}